// round 15
// baseline (speedup 1.0000x reference)
#include <cuda_runtime.h>
#include <cuda_bf16.h>
#include <cuda_fp16.h>
#include <cstdint>

#define NROWS 8192
#define HID   256
#define NTHREADS 256
#define BJ 64
#define JSPLIT 8
#define NCHSEG (NROWS / BJ / JSPLIT)   // 16 chunks per CTA

// ---------------- device scratch ----------------
__device__ __half g_qf[NROWS * HID];
__device__ __half g_kf[NROWS * HID];
__device__ __half g_vtf[HID * NROWS];              // [hid][token] fp16
__device__ __half g_ph[JSPLIT * NROWS * HID];      // fp16 partial O, all 8 segs
__device__ __half g_w16[3 * HID * HID];            // fp16 Wq|Wk|Wv
__device__ int    g_cnt[NROWS / 64];               // per-mtile arrival counter

// sigmoid via HW tanh
__device__ __forceinline__ float fsig(float x) {
    float t; asm("tanh.approx.f32 %0, %1;" : "=f"(t) : "f"(x * 0.5f));
    return fmaf(0.5f, t, 0.5f);
}
__device__ __forceinline__ uint32_t h2pack(float a, float b) {
    __half2 h = __floats2half2_rn(a, b);
    return *(uint32_t*)&h;
}
__device__ __forceinline__ uint32_t smem_to_u32(const void* p) {
    uint32_t a;
    asm("{ .reg .u64 t; cvta.to.shared.u64 t, %1; cvt.u32.u64 %0, t; }" : "=r"(a) : "l"(p));
    return a;
}
__device__ __forceinline__ void ldsm4(uint32_t r[4], uint32_t addr) {
    asm volatile("ldmatrix.sync.aligned.m8n8.x4.shared.b16 {%0,%1,%2,%3}, [%4];"
                 : "=r"(r[0]), "=r"(r[1]), "=r"(r[2]), "=r"(r[3]) : "r"(addr));
}
__device__ __forceinline__ void mma_f16(float c[4], const uint32_t a[4], uint32_t b0, uint32_t b1) {
    asm volatile("mma.sync.aligned.m16n8k16.row.col.f32.f16.f16.f32 "
                 "{%0,%1,%2,%3}, {%4,%5,%6,%7}, {%8,%9}, {%0,%1,%2,%3};"
                 : "+f"(c[0]), "+f"(c[1]), "+f"(c[2]), "+f"(c[3])
                 : "r"(a[0]), "r"(a[1]), "r"(a[2]), "r"(a[3]), "r"(b0), "r"(b1));
}
__device__ __forceinline__ void cpasync16(uint32_t saddr, const void* g) {
    asm volatile("cp.async.cg.shared.global [%0], [%1], 16;" :: "r"(saddr), "l"(g));
}
#define CP_COMMIT() asm volatile("cp.async.commit_group;" ::: "memory")
#define CP_WAIT(N)  asm volatile("cp.async.wait_group %0;" :: "n"(N) : "memory")
#define BAR_SYNC(id, cnt)   asm volatile("bar.sync %0, %1;"   :: "r"(id), "n"(cnt) : "memory")
#define BAR_ARRIVE(id, cnt) asm volatile("bar.arrive %0, %1;" :: "r"(id), "n"(cnt) : "memory")

// ---------------- W fp32 -> fp16 (once) + counter reset ----------------
__global__ __launch_bounds__(NTHREADS)
void wconv_kernel(const float* __restrict__ Wq, const float* __restrict__ Wk,
                  const float* __restrict__ Wv)
{
    if (blockIdx.y == 0 && blockIdx.x == 0 && threadIdx.x < NROWS / 64)
        g_cnt[threadIdx.x] = 0;
    const float* W = blockIdx.y == 0 ? Wq : (blockIdx.y == 1 ? Wk : Wv);
    __half* dst = g_w16 + (size_t)blockIdx.y * HID * HID;
    int i = (blockIdx.x * NTHREADS + threadIdx.x) * 4;
    float4 v = *(const float4*)(W + i);
    *(uint2*)(dst + i) = make_uint2(h2pack(v.x, v.y), h2pack(v.z, v.w));
}

// ================= HMMA linear: out = X @ W^T + b ===========================
// M=64 x N=128 tiles, 512 threads, 2 CTAs/SM.
// grid (128, 6): which = y>>1 (0=Q fp16, 1=K fp16, 2=V^T fp16), nhalf = y&1.
#define LST 528
#define LX_O 0
#define LW_O 33792
#define LSMEMB 101376

__global__ __launch_bounds__(512, 2)
void linear_hmma_kernel(const float* __restrict__ Xq, const float* __restrict__ Xk,
                        const float* __restrict__ Xv,
                        const float* __restrict__ bq, const float* __restrict__ bk,
                        const float* __restrict__ bv,
                        __half* __restrict__ qf, __half* __restrict__ kf,
                        __half* __restrict__ vtf)
{
    extern __shared__ __align__(128) char smem[];
    const uint32_t sb = smem_to_u32(smem);
    const int tid = threadIdx.x, wid = tid >> 5, lane = tid & 31;
    const int mw = wid & 1, nw = wid >> 1;          // M half (32) x N slice (16)
    const int row0 = blockIdx.x * 64;
    const int which = blockIdx.y >> 1;
    const int nhalf = blockIdx.y & 1;
    const int ncol0 = nhalf * 128;
    const int g = lane >> 3, rr = lane & 7;
    const int rr4 = lane >> 2, cc2 = (lane & 3) * 2;

    const float* X = which == 0 ? Xq : (which == 1 ? Xk : Xv);
    const __half* w16 = g_w16 + (size_t)which * HID * HID + (size_t)ncol0 * HID;
    const float* bias = which == 0 ? bq : (which == 1 ? bk : bv);

    for (int f = tid; f < 4096; f += 512) {
        int row = f >> 5, u = f & 31;
        cpasync16(sb + LW_O + row * LST + u * 16, w16 + (size_t)row * HID + u * 8);
    }
    CP_COMMIT();
    for (int f = tid; f < 4096; f += 512) {
        int row = f >> 6, c4 = (f & 63) << 2;
        float4 v = *(const float4*)(X + (size_t)(row0 + row) * HID + c4);
        *(uint2*)(smem + LX_O + row * LST + c4 * 2) =
            make_uint2(h2pack(v.x, v.y), h2pack(v.z, v.w));
    }
    CP_WAIT(0);
    __syncthreads();

    const uint32_t loA = (uint32_t)((rr + (g & 1) * 8) * LST + (g >> 1) * 16);
    const uint32_t loB = (uint32_t)((rr + (g >> 1) * 8) * LST + (g & 1) * 16);
    const uint32_t aX = sb + LX_O + (uint32_t)(mw * 32) * LST + loA;
    const uint32_t bW = sb + LW_O + (uint32_t)(nw * 16) * LST + loB;

    float acc[2][2][4];
#pragma unroll
    for (int a = 0; a < 2; a++)
#pragma unroll
        for (int b = 0; b < 2; b++)
#pragma unroll
            for (int c = 0; c < 4; c++) acc[a][b][c] = 0.0f;

#pragma unroll 8
    for (int ks = 0; ks < 16; ks++) {
        const uint32_t ko = (uint32_t)(ks * 32);
        uint32_t a0[4], a1[4], bh[4];
        ldsm4(a0, aX + ko);
        ldsm4(a1, aX + 16 * LST + ko);
        ldsm4(bh, bW + ko);
        mma_f16(acc[0][0], a0, bh[0], bh[1]); mma_f16(acc[0][1], a0, bh[2], bh[3]);
        mma_f16(acc[1][0], a1, bh[0], bh[1]); mma_f16(acc[1][1], a1, bh[2], bh[3]);
    }

    if (which == 2) {
        __syncthreads();
#pragma unroll
        for (int mf = 0; mf < 2; mf++)
#pragma unroll
            for (int j = 0; j < 2; j++) {
                const float* c = acc[mf][j];
                int ml = mw * 32 + mf * 16 + rr4;
                int cl = nw * 16 + j * 8 + cc2;
                float b0 = bias[ncol0 + cl], b1 = bias[ncol0 + cl + 1];
                *(__half*)(smem + cl * 128 + ml * 2)             = __float2half(c[0] + b0);
                *(__half*)(smem + (cl + 1) * 128 + ml * 2)       = __float2half(c[1] + b1);
                *(__half*)(smem + cl * 128 + (ml + 8) * 2)       = __float2half(c[2] + b0);
                *(__half*)(smem + (cl + 1) * 128 + (ml + 8) * 2) = __float2half(c[3] + b1);
            }
        __syncthreads();
        for (int f = tid; f < 1024; f += 512) {
            int row = f >> 3, u = f & 7;
            *(uint4*)(vtf + (size_t)(ncol0 + row) * NROWS + row0 + u * 8) =
                *(const uint4*)(smem + row * 128 + u * 16);
        }
    } else {
        __half* dst = which == 0 ? qf : kf;
#pragma unroll
        for (int mf = 0; mf < 2; mf++)
#pragma unroll
            for (int j = 0; j < 2; j++) {
                const float* c = acc[mf][j];
                int m = row0 + mw * 32 + mf * 16 + rr4;
                int col = ncol0 + nw * 16 + j * 8 + cc2;
                float b0 = bias[col], b1 = bias[col + 1];
                *(uint32_t*)(dst + (size_t)m * HID + col) = h2pack(c[0] + b0, c[1] + b1);
                *(uint32_t*)(dst + (size_t)(m + 8) * HID + col) = h2pack(c[2] + b0, c[3] + b1);
            }
    }
}

// ---------------- warp-specialized HMMA attention (j-split x8, P ring x4) ----
// Fused final reduction: every seg writes fp16 partial; last-arriving CTA per
// mtile sums all 8 partials in fixed seg order (deterministic) -> fp32 out.
#define STQ 528
#define STP 144
#define STV 144
#define Q_O    0
#define K_O    33792
#define KBUF   33792
#define V_O    101376
#define VBUF   36864
#define P_O    175104
#define PBUF   9216
#define PDEPTH 4
#define SMEMB  (P_O + PDEPTH * PBUF)   // 211968

__device__ __forceinline__ void stageK_async(uint32_t sb, int off, const __half* src,
                                             int r0, int t) {
    for (int f = t; f < 2048; f += 256) {
        int row = f >> 5, u = f & 31;
        cpasync16(sb + off + row * STQ + u * 16, src + (size_t)(r0 + row) * HID + u * 8);
    }
}
__device__ __forceinline__ void stageVt_async(uint32_t sb, int off, const __half* src,
                                              int j0, int t) {
    for (int f = t; f < 2048; f += 256) {
        int row = f >> 3, u = f & 7;
        cpasync16(sb + off + row * STV + u * 16, src + (size_t)row * NROWS + j0 + u * 8);
    }
}

__global__ __launch_bounds__(512)
void attn_kernel(float* __restrict__ out)
{
    extern __shared__ __align__(128) char smem[];
    const uint32_t sb = smem_to_u32(smem);
    const int tid = threadIdx.x, wid = tid >> 5, lane = tid & 31;
    const int t256 = tid & 255;
    const int w = wid & 7;
    const int mw = w & 1, nw = w >> 1;
    const int row0 = blockIdx.x * 64;
    const int jbase = blockIdx.y * (NROWS / JSPLIT);
    const int g = lane >> 3, rr = lane & 7;
    const int rr4 = lane >> 2, cc2 = (lane & 3) * 2;

    const uint32_t loA_Q = (uint32_t)((rr + (g & 1) * 8) * STQ + (g >> 1) * 16);
    const uint32_t loA_P = (uint32_t)((rr + (g & 1) * 8) * STP + (g >> 1) * 16);
    const uint32_t loB_K = (uint32_t)((rr + (g >> 1) * 8) * STQ + (g & 1) * 16);
    const uint32_t loB_V = (uint32_t)((rr + (g >> 1) * 8) * STV + (g & 1) * 16);

    if (wid < 8) {
        // ============ group A: MMA1 + sigmoid -> P ring ============
        stageK_async(sb, Q_O, g_qf, row0, t256);
        stageK_async(sb, K_O, g_kf, jbase, t256);
        CP_COMMIT();

        const uint32_t aQ  = sb + Q_O + (uint32_t)(mw * 32) * STQ + loA_Q;
        const uint32_t bKb = sb + K_O + (uint32_t)(nw * 16) * STQ + loB_K;

        for (int i = 0; i < NCHSEG; i++) {
            CP_WAIT(0);
            BAR_SYNC(1, 256);
            if (i + 1 < NCHSEG) {
                stageK_async(sb, K_O + ((i + 1) & 1) * KBUF, g_kf, jbase + (i + 1) * BJ, t256);
                CP_COMMIT();
            }

            float s[2][2][4];
#pragma unroll
            for (int a = 0; a < 2; a++)
#pragma unroll
                for (int b = 0; b < 2; b++)
#pragma unroll
                    for (int c = 0; c < 4; c++) s[a][b][c] = 0.0f;

            const uint32_t bK = bKb + (uint32_t)((i & 1) * KBUF);
#pragma unroll 8
            for (int ks = 0; ks < 16; ks++) {
                const uint32_t ko = (uint32_t)(ks * 32);
                uint32_t a0[4], a1[4], bh[4];
                ldsm4(a0, aQ + ko);
                ldsm4(a1, aQ + 16 * STQ + ko);
                ldsm4(bh, bK + ko);
                mma_f16(s[0][0], a0, bh[0], bh[1]); mma_f16(s[0][1], a0, bh[2], bh[3]);
                mma_f16(s[1][0], a1, bh[0], bh[1]); mma_f16(s[1][1], a1, bh[2], bh[3]);
            }

            uint32_t pk[2][2][2];
#pragma unroll
            for (int mf = 0; mf < 2; mf++)
#pragma unroll
                for (int nf = 0; nf < 2; nf++) {
                    const float* c = s[mf][nf];
                    pk[mf][nf][0] = h2pack(fsig(c[0]), fsig(c[1]));
                    pk[mf][nf][1] = h2pack(fsig(c[2]), fsig(c[3]));
                }

            if (i >= PDEPTH) BAR_SYNC(7 + (i & 3), 512);   // P[i&3] drained
            const uint32_t Pb = (uint32_t)(P_O + (i & 3) * PBUF);
#pragma unroll
            for (int mf = 0; mf < 2; mf++)
#pragma unroll
                for (int nf = 0; nf < 2; nf++) {
                    int m = mw * 32 + mf * 16 + rr4;
                    int n = nw * 16 + nf * 8 + cc2;
                    *(uint32_t*)(smem + Pb + m * STP + n * 2) = pk[mf][nf][0];
                    *(uint32_t*)(smem + Pb + (m + 8) * STP + n * 2) = pk[mf][nf][1];
                }
            __threadfence_block();
            BAR_ARRIVE(3 + (i & 3), 512);                  // P[i&3] full
        }
    } else {
        // ============ group B: MMA2 ============
        stageVt_async(sb, V_O, g_vtf, jbase, t256);
        CP_COMMIT();

        float oacc[2][8][4];
#pragma unroll
        for (int a = 0; a < 2; a++)
#pragma unroll
            for (int b = 0; b < 8; b++)
#pragma unroll
                for (int c = 0; c < 4; c++) oacc[a][b][c] = 0.0f;

        const uint32_t aPb = sb + P_O + (uint32_t)(mw * 32) * STP + loA_P;
        const uint32_t bVb = sb + V_O + (uint32_t)(nw * 64) * STV + loB_V;

        for (int i = 0; i < NCHSEG; i++) {
            BAR_SYNC(3 + (i & 3), 512);                    // P[i&3] full
            CP_WAIT(0);
            BAR_SYNC(2, 256);                              // V[i&1] visible
            if (i + 1 < NCHSEG) {
                stageVt_async(sb, V_O + ((i + 1) & 1) * VBUF, g_vtf, jbase + (i + 1) * BJ, t256);
                CP_COMMIT();
            }

            const uint32_t aP = aPb + (uint32_t)((i & 3) * PBUF);
            const uint32_t bV = bVb + (uint32_t)((i & 1) * VBUF);
#pragma unroll
            for (int ks = 0; ks < 4; ks++) {
                const uint32_t ko = (uint32_t)(ks * 32);
                uint32_t p0[4], p1[4];
                ldsm4(p0, aP + ko);
                ldsm4(p1, aP + 16 * STP + ko);
#pragma unroll
                for (int t = 0; t < 4; t++) {
                    uint32_t bh[4];
                    ldsm4(bh, bV + (uint32_t)(t * 16) * STV + ko);
                    mma_f16(oacc[0][t * 2], p0, bh[0], bh[1]);
                    mma_f16(oacc[0][t * 2 + 1], p0, bh[2], bh[3]);
                    mma_f16(oacc[1][t * 2], p1, bh[0], bh[1]);
                    mma_f16(oacc[1][t * 2 + 1], p1, bh[2], bh[3]);
                }
            }
            BAR_ARRIVE(7 + (i & 3), 512);                  // P[i&3] empty
        }

        // epilogue: every seg writes fp16 partial
        {
            __half* php = g_ph + (size_t)blockIdx.y * NROWS * HID;
#pragma unroll
            for (int mf = 0; mf < 2; mf++)
#pragma unroll
                for (int j = 0; j < 8; j++) {
                    const float* c = oacc[mf][j];
                    int m = row0 + mw * 32 + mf * 16 + rr4;
                    int col = nw * 64 + (j >> 1) * 16 + (j & 1) * 8 + cc2;
                    *(uint32_t*)(php + (size_t)m * HID + col) = h2pack(c[0], c[1]);
                    *(uint32_t*)(php + (size_t)(m + 8) * HID + col) = h2pack(c[2], c[3]);
                }
        }

        // last-arriving CTA of this mtile sums all 8 partials (fixed order)
        __threadfence();
        if (t256 == 0)
            *(volatile int*)smem = atomicAdd(&g_cnt[blockIdx.x], 1);
        BAR_SYNC(11, 256);
        int arrived = *(volatile int*)smem;
        if (arrived == JSPLIT - 1) {
            const size_t base = (size_t)row0 * HID;        // 16384 contiguous floats
            for (int u = t256; u < 4096; u += 256) {       // 4 floats per unit
                float4 acc4 = make_float4(0.f, 0.f, 0.f, 0.f);
#pragma unroll
                for (int s = 0; s < JSPLIT; s++) {
                    const uint2* p = (const uint2*)(g_ph + (size_t)s * NROWS * HID + base) + u;
                    uint2 b = __ldcg(p);
                    __half2 h0 = *(__half2*)&b.x, h1 = *(__half2*)&b.y;
                    float2 f0 = __half22float2(h0), f1 = __half22float2(h1);
                    acc4.x += f0.x; acc4.y += f0.y; acc4.z += f1.x; acc4.w += f1.y;
                }
                *(float4*)(out + base + (size_t)u * 4) = acc4;
            }
        }
    }
}

// ---------------------------------------------------------------------------
extern "C" void kernel_launch(void* const* d_in, const int* in_sizes, int n_in,
                              void* d_out, int out_size)
{
    const float* query = (const float*)d_in[0];
    const float* key_  = (const float*)d_in[1];
    const float* value = (const float*)d_in[2];
    const float* Wq = (const float*)d_in[3];
    const float* bq = (const float*)d_in[4];
    const float* Wk = (const float*)d_in[5];
    const float* bk = (const float*)d_in[6];
    const float* Wv = (const float*)d_in[7];
    const float* bv = (const float*)d_in[8];
    float* out = (float*)d_out;
    (void)in_sizes; (void)n_in; (void)out_size;

    __half *qf, *kf, *vtf;
    cudaGetSymbolAddress((void**)&qf, g_qf);
    cudaGetSymbolAddress((void**)&kf, g_kf);
    cudaGetSymbolAddress((void**)&vtf, g_vtf);

    wconv_kernel<<<dim3(HID * HID / 4 / NTHREADS, 3), NTHREADS>>>(Wq, Wk, Wv);

    cudaFuncSetAttribute(linear_hmma_kernel, cudaFuncAttributeMaxDynamicSharedMemorySize, LSMEMB);
    linear_hmma_kernel<<<dim3(NROWS / 64, 6), 512, LSMEMB>>>(
        query, key_, value, bq, bk, bv, qf, kf, vtf);

    cudaFuncSetAttribute(attn_kernel, cudaFuncAttributeMaxDynamicSharedMemorySize, SMEMB);
    attn_kernel<<<dim3(NROWS / 64, JSPLIT), 512, SMEMB>>>(out);
}

// round 16
// speedup vs baseline: 1.0379x; 1.0379x over previous
#include <cuda_runtime.h>
#include <cuda_bf16.h>
#include <cuda_fp16.h>
#include <cstdint>

#define NROWS 8192
#define HID   256
#define NTHREADS 256
#define BJ 64
#define JSPLIT 8
#define NCHSEG (NROWS / BJ / JSPLIT)   // 16 chunks per CTA

// ---------------- device scratch ----------------
__device__ __half g_qf[NROWS * HID];
__device__ __half g_kf[NROWS * HID];
__device__ __half g_vtf[HID * NROWS];                  // [hid][token] fp16
__device__ __half g_ph[(JSPLIT - 1) * NROWS * HID];    // fp16 partial O, jseg 1..7
__device__ __half g_w16[3 * HID * HID];                // fp16 Wq|Wk|Wv

// sigmoid via HW tanh
__device__ __forceinline__ float fsig(float x) {
    float t; asm("tanh.approx.f32 %0, %1;" : "=f"(t) : "f"(x * 0.5f));
    return fmaf(0.5f, t, 0.5f);
}
__device__ __forceinline__ uint32_t h2pack(float a, float b) {
    __half2 h = __floats2half2_rn(a, b);
    return *(uint32_t*)&h;
}
__device__ __forceinline__ uint32_t smem_to_u32(const void* p) {
    uint32_t a;
    asm("{ .reg .u64 t; cvta.to.shared.u64 t, %1; cvt.u32.u64 %0, t; }" : "=r"(a) : "l"(p));
    return a;
}
__device__ __forceinline__ void ldsm4(uint32_t r[4], uint32_t addr) {
    asm volatile("ldmatrix.sync.aligned.m8n8.x4.shared.b16 {%0,%1,%2,%3}, [%4];"
                 : "=r"(r[0]), "=r"(r[1]), "=r"(r[2]), "=r"(r[3]) : "r"(addr));
}
__device__ __forceinline__ void mma_f16(float c[4], const uint32_t a[4], uint32_t b0, uint32_t b1) {
    asm volatile("mma.sync.aligned.m16n8k16.row.col.f32.f16.f16.f32 "
                 "{%0,%1,%2,%3}, {%4,%5,%6,%7}, {%8,%9}, {%0,%1,%2,%3};"
                 : "+f"(c[0]), "+f"(c[1]), "+f"(c[2]), "+f"(c[3])
                 : "r"(a[0]), "r"(a[1]), "r"(a[2]), "r"(a[3]), "r"(b0), "r"(b1));
}
__device__ __forceinline__ void cpasync16(uint32_t saddr, const void* g) {
    asm volatile("cp.async.cg.shared.global [%0], [%1], 16;" :: "r"(saddr), "l"(g));
}
#define CP_COMMIT() asm volatile("cp.async.commit_group;" ::: "memory")
#define CP_WAIT(N)  asm volatile("cp.async.wait_group %0;" :: "n"(N) : "memory")
#define BAR_SYNC(id, cnt)   asm volatile("bar.sync %0, %1;"   :: "r"(id), "n"(cnt) : "memory")
#define BAR_ARRIVE(id, cnt) asm volatile("bar.arrive %0, %1;" :: "r"(id), "n"(cnt) : "memory")

// ---------------- W fp32 -> fp16 (once) ----------------
__global__ __launch_bounds__(NTHREADS)
void wconv_kernel(const float* __restrict__ Wq, const float* __restrict__ Wk,
                  const float* __restrict__ Wv)
{
    const float* W = blockIdx.y == 0 ? Wq : (blockIdx.y == 1 ? Wk : Wv);
    __half* dst = g_w16 + (size_t)blockIdx.y * HID * HID;
    int i = (blockIdx.x * NTHREADS + threadIdx.x) * 4;
    float4 v = *(const float4*)(W + i);
    *(uint2*)(dst + i) = make_uint2(h2pack(v.x, v.y), h2pack(v.z, v.w));
}

// ================= HMMA linear: out = X @ W^T + b ===========================
// M=64 x N=128 tiles, 512 threads, 2 CTAs/SM.
// grid (128, 6): which = y>>1 (0=Q fp16, 1=K fp16, 2=V^T fp16), nhalf = y&1.
#define LST 528
#define LX_O 0
#define LW_O 33792
#define LSMEMB 101376

__global__ __launch_bounds__(512, 2)
void linear_hmma_kernel(const float* __restrict__ Xq, const float* __restrict__ Xk,
                        const float* __restrict__ Xv,
                        const float* __restrict__ bq, const float* __restrict__ bk,
                        const float* __restrict__ bv,
                        __half* __restrict__ qf, __half* __restrict__ kf,
                        __half* __restrict__ vtf)
{
    extern __shared__ __align__(128) char smem[];
    const uint32_t sb = smem_to_u32(smem);
    const int tid = threadIdx.x, wid = tid >> 5, lane = tid & 31;
    const int mw = wid & 1, nw = wid >> 1;          // M half (32) x N slice (16)
    const int row0 = blockIdx.x * 64;
    const int which = blockIdx.y >> 1;
    const int nhalf = blockIdx.y & 1;
    const int ncol0 = nhalf * 128;
    const int g = lane >> 3, rr = lane & 7;
    const int rr4 = lane >> 2, cc2 = (lane & 3) * 2;

    const float* X = which == 0 ? Xq : (which == 1 ? Xk : Xv);
    const __half* w16 = g_w16 + (size_t)which * HID * HID + (size_t)ncol0 * HID;
    const float* bias = which == 0 ? bq : (which == 1 ? bk : bv);

    for (int f = tid; f < 4096; f += 512) {
        int row = f >> 5, u = f & 31;
        cpasync16(sb + LW_O + row * LST + u * 16, w16 + (size_t)row * HID + u * 8);
    }
    CP_COMMIT();
    for (int f = tid; f < 4096; f += 512) {
        int row = f >> 6, c4 = (f & 63) << 2;
        float4 v = *(const float4*)(X + (size_t)(row0 + row) * HID + c4);
        *(uint2*)(smem + LX_O + row * LST + c4 * 2) =
            make_uint2(h2pack(v.x, v.y), h2pack(v.z, v.w));
    }
    CP_WAIT(0);
    __syncthreads();

    const uint32_t loA = (uint32_t)((rr + (g & 1) * 8) * LST + (g >> 1) * 16);
    const uint32_t loB = (uint32_t)((rr + (g >> 1) * 8) * LST + (g & 1) * 16);
    const uint32_t aX = sb + LX_O + (uint32_t)(mw * 32) * LST + loA;
    const uint32_t bW = sb + LW_O + (uint32_t)(nw * 16) * LST + loB;

    float acc[2][2][4];
#pragma unroll
    for (int a = 0; a < 2; a++)
#pragma unroll
        for (int b = 0; b < 2; b++)
#pragma unroll
            for (int c = 0; c < 4; c++) acc[a][b][c] = 0.0f;

#pragma unroll 8
    for (int ks = 0; ks < 16; ks++) {
        const uint32_t ko = (uint32_t)(ks * 32);
        uint32_t a0[4], a1[4], bh[4];
        ldsm4(a0, aX + ko);
        ldsm4(a1, aX + 16 * LST + ko);
        ldsm4(bh, bW + ko);
        mma_f16(acc[0][0], a0, bh[0], bh[1]); mma_f16(acc[0][1], a0, bh[2], bh[3]);
        mma_f16(acc[1][0], a1, bh[0], bh[1]); mma_f16(acc[1][1], a1, bh[2], bh[3]);
    }

    if (which == 2) {
        __syncthreads();
#pragma unroll
        for (int mf = 0; mf < 2; mf++)
#pragma unroll
            for (int j = 0; j < 2; j++) {
                const float* c = acc[mf][j];
                int ml = mw * 32 + mf * 16 + rr4;
                int cl = nw * 16 + j * 8 + cc2;
                float b0 = bias[ncol0 + cl], b1 = bias[ncol0 + cl + 1];
                *(__half*)(smem + cl * 128 + ml * 2)             = __float2half(c[0] + b0);
                *(__half*)(smem + (cl + 1) * 128 + ml * 2)       = __float2half(c[1] + b1);
                *(__half*)(smem + cl * 128 + (ml + 8) * 2)       = __float2half(c[2] + b0);
                *(__half*)(smem + (cl + 1) * 128 + (ml + 8) * 2) = __float2half(c[3] + b1);
            }
        __syncthreads();
        for (int f = tid; f < 1024; f += 512) {
            int row = f >> 3, u = f & 7;
            *(uint4*)(vtf + (size_t)(ncol0 + row) * NROWS + row0 + u * 8) =
                *(const uint4*)(smem + row * 128 + u * 16);
        }
    } else {
        __half* dst = which == 0 ? qf : kf;
#pragma unroll
        for (int mf = 0; mf < 2; mf++)
#pragma unroll
            for (int j = 0; j < 2; j++) {
                const float* c = acc[mf][j];
                int m = row0 + mw * 32 + mf * 16 + rr4;
                int col = ncol0 + nw * 16 + j * 8 + cc2;
                float b0 = bias[col], b1 = bias[col + 1];
                *(uint32_t*)(dst + (size_t)m * HID + col) = h2pack(c[0] + b0, c[1] + b1);
                *(uint32_t*)(dst + (size_t)(m + 8) * HID + col) = h2pack(c[2] + b0, c[3] + b1);
            }
    }
}

// ---------------- warp-specialized HMMA attention (j-split x8, P ring x4) ----
#define STQ 528
#define STP 144
#define STV 144
#define Q_O    0
#define K_O    33792
#define KBUF   33792
#define V_O    101376
#define VBUF   36864
#define P_O    175104
#define PBUF   9216
#define PDEPTH 4
#define SMEMB  (P_O + PDEPTH * PBUF)   // 211968

__device__ __forceinline__ void stageK_async(uint32_t sb, int off, const __half* src,
                                             int r0, int t) {
    for (int f = t; f < 2048; f += 256) {
        int row = f >> 5, u = f & 31;
        cpasync16(sb + off + row * STQ + u * 16, src + (size_t)(r0 + row) * HID + u * 8);
    }
}
__device__ __forceinline__ void stageVt_async(uint32_t sb, int off, const __half* src,
                                              int j0, int t) {
    for (int f = t; f < 2048; f += 256) {
        int row = f >> 3, u = f & 7;
        cpasync16(sb + off + row * STV + u * 16, src + (size_t)row * NROWS + j0 + u * 8);
    }
}

__global__ __launch_bounds__(512)
void attn_kernel(float* __restrict__ out)
{
    extern __shared__ __align__(128) char smem[];
    const uint32_t sb = smem_to_u32(smem);
    const int tid = threadIdx.x, wid = tid >> 5, lane = tid & 31;
    const int t256 = tid & 255;
    const int w = wid & 7;
    const int mw = w & 1, nw = w >> 1;
    const int row0 = blockIdx.x * 64;
    const int jbase = blockIdx.y * (NROWS / JSPLIT);
    const int g = lane >> 3, rr = lane & 7;
    const int rr4 = lane >> 2, cc2 = (lane & 3) * 2;

    const uint32_t loA_Q = (uint32_t)((rr + (g & 1) * 8) * STQ + (g >> 1) * 16);
    const uint32_t loA_P = (uint32_t)((rr + (g & 1) * 8) * STP + (g >> 1) * 16);
    const uint32_t loB_K = (uint32_t)((rr + (g >> 1) * 8) * STQ + (g & 1) * 16);
    const uint32_t loB_V = (uint32_t)((rr + (g >> 1) * 8) * STV + (g & 1) * 16);

    if (wid < 8) {
        // ============ group A: MMA1 + sigmoid -> P ring ============
        stageK_async(sb, Q_O, g_qf, row0, t256);
        stageK_async(sb, K_O, g_kf, jbase, t256);
        CP_COMMIT();

        const uint32_t aQ  = sb + Q_O + (uint32_t)(mw * 32) * STQ + loA_Q;
        const uint32_t bKb = sb + K_O + (uint32_t)(nw * 16) * STQ + loB_K;

        for (int i = 0; i < NCHSEG; i++) {
            CP_WAIT(0);
            BAR_SYNC(1, 256);
            if (i + 1 < NCHSEG) {
                stageK_async(sb, K_O + ((i + 1) & 1) * KBUF, g_kf, jbase + (i + 1) * BJ, t256);
                CP_COMMIT();
            }

            float s[2][2][4];
#pragma unroll
            for (int a = 0; a < 2; a++)
#pragma unroll
                for (int b = 0; b < 2; b++)
#pragma unroll
                    for (int c = 0; c < 4; c++) s[a][b][c] = 0.0f;

            const uint32_t bK = bKb + (uint32_t)((i & 1) * KBUF);
#pragma unroll 8
            for (int ks = 0; ks < 16; ks++) {
                const uint32_t ko = (uint32_t)(ks * 32);
                uint32_t a0[4], a1[4], bh[4];
                ldsm4(a0, aQ + ko);
                ldsm4(a1, aQ + 16 * STQ + ko);
                ldsm4(bh, bK + ko);
                mma_f16(s[0][0], a0, bh[0], bh[1]); mma_f16(s[0][1], a0, bh[2], bh[3]);
                mma_f16(s[1][0], a1, bh[0], bh[1]); mma_f16(s[1][1], a1, bh[2], bh[3]);
            }

            uint32_t pk[2][2][2];
#pragma unroll
            for (int mf = 0; mf < 2; mf++)
#pragma unroll
                for (int nf = 0; nf < 2; nf++) {
                    const float* c = s[mf][nf];
                    pk[mf][nf][0] = h2pack(fsig(c[0]), fsig(c[1]));
                    pk[mf][nf][1] = h2pack(fsig(c[2]), fsig(c[3]));
                }

            if (i >= PDEPTH) BAR_SYNC(7 + (i & 3), 512);   // P[i&3] drained
            const uint32_t Pb = (uint32_t)(P_O + (i & 3) * PBUF);
#pragma unroll
            for (int mf = 0; mf < 2; mf++)
#pragma unroll
                for (int nf = 0; nf < 2; nf++) {
                    int m = mw * 32 + mf * 16 + rr4;
                    int n = nw * 16 + nf * 8 + cc2;
                    *(uint32_t*)(smem + Pb + m * STP + n * 2) = pk[mf][nf][0];
                    *(uint32_t*)(smem + Pb + (m + 8) * STP + n * 2) = pk[mf][nf][1];
                }
            __threadfence_block();
            BAR_ARRIVE(3 + (i & 3), 512);                  // P[i&3] full
        }
    } else {
        // ============ group B: MMA2 ============
        stageVt_async(sb, V_O, g_vtf, jbase, t256);
        CP_COMMIT();

        float oacc[2][8][4];
#pragma unroll
        for (int a = 0; a < 2; a++)
#pragma unroll
            for (int b = 0; b < 8; b++)
#pragma unroll
                for (int c = 0; c < 4; c++) oacc[a][b][c] = 0.0f;

        const uint32_t aPb = sb + P_O + (uint32_t)(mw * 32) * STP + loA_P;
        const uint32_t bVb = sb + V_O + (uint32_t)(nw * 64) * STV + loB_V;

        for (int i = 0; i < NCHSEG; i++) {
            BAR_SYNC(3 + (i & 3), 512);                    // P[i&3] full
            CP_WAIT(0);
            BAR_SYNC(2, 256);                              // V[i&1] visible
            if (i + 1 < NCHSEG) {
                stageVt_async(sb, V_O + ((i + 1) & 1) * VBUF, g_vtf, jbase + (i + 1) * BJ, t256);
                CP_COMMIT();
            }

            const uint32_t aP = aPb + (uint32_t)((i & 3) * PBUF);
            const uint32_t bV = bVb + (uint32_t)((i & 1) * VBUF);
#pragma unroll
            for (int ks = 0; ks < 4; ks++) {
                const uint32_t ko = (uint32_t)(ks * 32);
                uint32_t p0[4], p1[4];
                ldsm4(p0, aP + ko);
                ldsm4(p1, aP + 16 * STP + ko);
#pragma unroll
                for (int t = 0; t < 4; t++) {
                    uint32_t bh[4];
                    ldsm4(bh, bV + (uint32_t)(t * 16) * STV + ko);
                    mma_f16(oacc[0][t * 2], p0, bh[0], bh[1]);
                    mma_f16(oacc[0][t * 2 + 1], p0, bh[2], bh[3]);
                    mma_f16(oacc[1][t * 2], p1, bh[0], bh[1]);
                    mma_f16(oacc[1][t * 2 + 1], p1, bh[2], bh[3]);
                }
            }
            BAR_ARRIVE(7 + (i & 3), 512);                  // P[i&3] empty
        }

        // epilogue: jseg 0 -> fp32 out ; jseg 1..7 -> fp16 partial
        if (blockIdx.y == 0) {
#pragma unroll
            for (int mf = 0; mf < 2; mf++)
#pragma unroll
                for (int j = 0; j < 8; j++) {
                    const float* c = oacc[mf][j];
                    int m = row0 + mw * 32 + mf * 16 + rr4;
                    int col = nw * 64 + (j >> 1) * 16 + (j & 1) * 8 + cc2;
                    *(float2*)(out + (size_t)m * HID + col) = make_float2(c[0], c[1]);
                    *(float2*)(out + (size_t)(m + 8) * HID + col) = make_float2(c[2], c[3]);
                }
        } else {
            __half* php = g_ph + (size_t)(blockIdx.y - 1) * NROWS * HID;
#pragma unroll
            for (int mf = 0; mf < 2; mf++)
#pragma unroll
                for (int j = 0; j < 8; j++) {
                    const float* c = oacc[mf][j];
                    int m = row0 + mw * 32 + mf * 16 + rr4;
                    int col = nw * 64 + (j >> 1) * 16 + (j & 1) * 8 + cc2;
                    *(uint32_t*)(php + (size_t)m * HID + col) = h2pack(c[0], c[1]);
                    *(uint32_t*)(php + (size_t)(m + 8) * HID + col) = h2pack(c[2], c[3]);
                }
        }
    }
}

// ---------------- deterministic reduce of fp16 partials (8 floats/thread) ----
__global__ __launch_bounds__(NTHREADS)
void reduce_kernel(float* __restrict__ out)
{
    size_t i = ((size_t)blockIdx.x * NTHREADS + threadIdx.x) * 8;
    float4 a0 = *(float4*)(out + i);
    float4 a1 = *(float4*)(out + i + 4);
#pragma unroll
    for (int s = 0; s < JSPLIT - 1; s++) {
        uint4 b = __ldcg((const uint4*)(g_ph + (size_t)s * NROWS * HID + i));
        __half2 h0 = *(__half2*)&b.x, h1 = *(__half2*)&b.y;
        __half2 h2 = *(__half2*)&b.z, h3 = *(__half2*)&b.w;
        float2 f0 = __half22float2(h0), f1 = __half22float2(h1);
        float2 f2 = __half22float2(h2), f3 = __half22float2(h3);
        a0.x += f0.x; a0.y += f0.y; a0.z += f1.x; a0.w += f1.y;
        a1.x += f2.x; a1.y += f2.y; a1.z += f3.x; a1.w += f3.y;
    }
    *(float4*)(out + i) = a0;
    *(float4*)(out + i + 4) = a1;
}

// ---------------------------------------------------------------------------
extern "C" void kernel_launch(void* const* d_in, const int* in_sizes, int n_in,
                              void* d_out, int out_size)
{
    const float* query = (const float*)d_in[0];
    const float* key_  = (const float*)d_in[1];
    const float* value = (const float*)d_in[2];
    const float* Wq = (const float*)d_in[3];
    const float* bq = (const float*)d_in[4];
    const float* Wk = (const float*)d_in[5];
    const float* bk = (const float*)d_in[6];
    const float* Wv = (const float*)d_in[7];
    const float* bv = (const float*)d_in[8];
    float* out = (float*)d_out;
    (void)in_sizes; (void)n_in; (void)out_size;

    __half *qf, *kf, *vtf;
    cudaGetSymbolAddress((void**)&qf, g_qf);
    cudaGetSymbolAddress((void**)&kf, g_kf);
    cudaGetSymbolAddress((void**)&vtf, g_vtf);

    wconv_kernel<<<dim3(HID * HID / 4 / NTHREADS, 3), NTHREADS>>>(Wq, Wk, Wv);

    cudaFuncSetAttribute(linear_hmma_kernel, cudaFuncAttributeMaxDynamicSharedMemorySize, LSMEMB);
    linear_hmma_kernel<<<dim3(NROWS / 64, 6), 512, LSMEMB>>>(
        query, key_, value, bq, bk, bv, qf, kf, vtf);

    cudaFuncSetAttribute(attn_kernel, cudaFuncAttributeMaxDynamicSharedMemorySize, SMEMB);
    attn_kernel<<<dim3(NROWS / 64, JSPLIT), 512, SMEMB>>>(out);

    reduce_kernel<<<NROWS * HID / 8 / NTHREADS, NTHREADS>>>(out);
}